// round 12
// baseline (speedup 1.0000x reference)
#include <cuda_runtime.h>

// Problem constants
#define B_DIM 8
#define D_DIM 40
#define H_DIM 32
#define W_DIM 88
#define C_DIM 80
#define QUADS (C_DIM / 4)
#define NX 256
#define NY 256
#define NCELL (NX * NY)                      // 65536 cells per batch
#define NPTS (B_DIM * D_DIM * H_DIM * W_DIM) // 901120 points
#define NROWS (B_DIM * D_DIM * H_DIM)        // 10240 rows of 88
// NZ = 1

// Scratch accumulator (cell-major): (B, NCELL, C) fp32 = 168 MB. .bss zero.
// Entry invariant (maintained by transpose_zero_kernel): count table all-zero;
// every cell that will have count>=2 is zero (count==1 cells are fully
// overwritten by the sole-store; count==0 cells are never read).
__device__ float g_scratch[(long long)B_DIM * NCELL * C_DIM];
// Per-(b,cell) contributor count: 524288 ints = 2 MB. .bss zero.
__device__ int g_count[B_DIM * NCELL];
// Cached flat cell index per point (-1 = out of bounds): 3.6 MB.
__device__ int g_flat[NPTS];

// ---------------------------------------------------------------------------
// Count pass: one thread per point. Computes the cell index (cached into
// g_flat) and bumps the per-(b,cell) contributor count.
// ---------------------------------------------------------------------------
__global__ void __launch_bounds__(256) count_kernel(
    const float* __restrict__ geom)   // (B, D, H, W, 3)
{
    const int n = blockIdx.x * 256 + threadIdx.x;   // 0 .. NPTS-1 (exact grid)
    const float* g = geom + (long long)n * 3;
    const float gx = g[0];
    const float gy = g[1];
    const float gz = g[2];

    int flat = -1;
    if (gx >= -51.2f && gx < 51.2f &&
        gy >= -51.2f && gy < 51.2f &&
        gz >= -10.0f && gz < 10.0f) {
        // Match XLA: div-by-const lowered to mul-by-reciprocal (1/0.4 == 2.5f
        // exactly in fp32). add-then-mul cannot be FMA-contracted.
        const float rx = (gx + 51.2f) * 2.5f;
        const float ry = (gy + 51.2f) * 2.5f;
        int ix = (int)rx;
        int iy = (int)ry;
        ix = min(max(ix, 0), NX - 1);
        iy = min(max(iy, 0), NY - 1);
        flat = ix * NY + iy;
    }
    g_flat[n] = flat;
    if (flat >= 0) {
        const int b = n / (D_DIM * H_DIM * W_DIM);
        atomicAdd(&g_count[b * NCELL + flat], 1);   // RED (no return)
    }
}

// ---------------------------------------------------------------------------
// Scatter: one block of 352 threads per (b, d, h) row of W=88 points.
// blockDim = 352 = 4*88 makes the (q, w) mapping loop-invariant per thread:
//   idx = t + k*352  ->  w = t % 88 (constant), q = t/88 + 4k, k = 0..4.
// So each thread reads its cell index ONCE, and the k-loop fully unrolls
// into 20 independent evict-first loads + 5 stores/REDs (high MLP, no
// per-iteration division, branch hoisted out of the loop).
// Sole contributor -> plain STG.128 (value + initialization, no LTS atomic);
// otherwise red.global.add.v4.f32 onto the pre-zeroed base.
// ---------------------------------------------------------------------------
__global__ void __launch_bounds__(352) scatter_kernel(
    const float* __restrict__ x)      // (B, D, C, H, W)
{
    __shared__ int s_flat[W_DIM];
    __shared__ int s_cnt[W_DIM];

    const int bid = blockIdx.x;           // 0 .. NROWS-1
    const int h   = bid % H_DIM;
    const int bd  = bid / H_DIM;
    const int d   = bd % D_DIM;
    const int b   = bd / D_DIM;

    const int t = threadIdx.x;

    if (t < W_DIM) {
        const int flat = g_flat[bid * W_DIM + t];
        s_flat[t] = flat;
        s_cnt[t]  = (flat >= 0) ? __ldg(&g_count[b * NCELL + flat]) : 0;
    }
    __syncthreads();

    const int w  = t % W_DIM;             // constant per thread
    const int q0 = t / W_DIM;             // 0..3

    const int flat = s_flat[w];
    if (flat < 0) return;
    const int cnt = s_cnt[w];

    // x index: (((b*D+d)*C + c)*H + h)*W + w ; c = 4*(q0+4k)+j
    const long long x_base = ((long long)(b * D_DIM + d) * C_DIM * H_DIM + h) * W_DIM;
    const int c_stride = H_DIM * W_DIM;                       // 2816
    const float* xp0 = x + x_base + (long long)(q0 * 4) * c_stride + w;
    const long long k_step = (long long)16 * c_stride;        // 4 quads

    float* const dst0 = g_scratch + ((long long)b * NCELL + flat) * C_DIM + q0 * 4;

    if (cnt == 1) {
        #pragma unroll
        for (int k = 0; k < 5; k++) {
            const float* xp = xp0 + k * k_step;
            float v0 = __ldcs(xp);
            float v1 = __ldcs(xp + c_stride);
            float v2 = __ldcs(xp + 2 * c_stride);
            float v3 = __ldcs(xp + 3 * c_stride);
            // Sole contributor: plain vec store = value + initialization.
            *(float4*)(dst0 + k * 16) = make_float4(v0, v1, v2, v3);
        }
    } else {
        #pragma unroll
        for (int k = 0; k < 5; k++) {
            const float* xp = xp0 + k * k_step;
            float v0 = __ldcs(xp);
            float v1 = __ldcs(xp + c_stride);
            float v2 = __ldcs(xp + 2 * c_stride);
            float v3 = __ldcs(xp + 3 * c_stride);
            asm volatile("red.global.add.v4.f32 [%0], {%1, %2, %3, %4};"
                         :: "l"(dst0 + k * 16), "f"(v0), "f"(v1), "f"(v2), "f"(v3)
                         : "memory");
        }
    }
}

// ---------------------------------------------------------------------------
// Transpose + state restore: scratch (B, NCELL, C) -> out (B, C, NCELL).
// 128 cells x 80 channels per block (10 global loads/thread for MLP).
//  - count==0 cells synthesized as zeros (no scratch read).
//  - Store phase: conflict-free scalar LDS (stride 81 == 17 mod 32) +
//    perfectly coalesced STG.32.
//  - Afterwards (well past the loads): zero the scratch of count>=2 cells
//    and zero the count words, restoring the entry invariant.
// ---------------------------------------------------------------------------
__global__ void __launch_bounds__(256) transpose_zero_kernel(float* __restrict__ out)
{
    __shared__ float tile[128][81];
    __shared__ int s_cnt[128];

    const int blk   = blockIdx.x;            // 0 .. B*512-1
    const int b     = blk >> 9;
    const int tile0 = (blk & 511) * 128;     // first cell of tile
    const int t     = threadIdx.x;

    if (t < 128) s_cnt[t] = __ldg(&g_count[b * NCELL + tile0 + t]);
    __syncthreads();

    float4* const src = (float4*)(g_scratch +
                        ((long long)b * NCELL + tile0) * C_DIM);

    // Load: 128 cells * 20 float4 = 2560 vec loads (10/thread), coalesced;
    // empty cells synthesized as zero without touching global.
    #pragma unroll
    for (int k = 0; k < 10; k++) {
        const int i    = t + k * 256;
        const int cell = i / 20;
        const int q    = i - cell * 20;
        float4 v = make_float4(0.f, 0.f, 0.f, 0.f);
        if (s_cnt[cell] > 0) v = __ldcs(&src[i]);
        tile[cell][q * 4 + 0] = v.x;
        tile[cell][q * 4 + 1] = v.y;
        tile[cell][q * 4 + 2] = v.z;
        tile[cell][q * 4 + 3] = v.w;
    }
    __syncthreads();

    // Store: 80 channels * 128 cells, scalar (40/thread). Lanes cover 32
    // consecutive cells of one channel: LDS conflict-free, STG.32 coalesced.
    float* ob = out + (long long)b * C_DIM * NCELL + tile0;
    #pragma unroll
    for (int k = 0; k < 40; k++) {
        const int i    = t + k * 256;
        const int c    = i >> 7;       // / 128
        const int cell = i & 127;
        __stcs(ob + (long long)c * NCELL + cell, tile[cell][c]);
    }

    // Restore scratch zeros for cells that needed a zero base this call
    // (count>=2). count==1 cells will be overwritten by next call's sole
    // store; count==0 cells are never read.
    #pragma unroll
    for (int k = 0; k < 10; k++) {
        const int i    = t + k * 256;
        const int cell = i / 20;
        if (s_cnt[cell] >= 2) {
            src[i] = make_float4(0.f, 0.f, 0.f, 0.f);
        }
    }

    // Restore count words to zero (128 ints = 32 int4).
    if (t < 32) {
        ((int4*)(g_count + b * NCELL + tile0))[t] = make_int4(0, 0, 0, 0);
    }
}

extern "C" void kernel_launch(void* const* d_in, const int* in_sizes, int n_in,
                              void* d_out, int out_size) {
    const float* geom = (const float*)d_in[0];   // (8,40,32,88,3)
    const float* x    = (const float*)d_in[1];   // (8,40,80,32,88)
    float* out        = (float*)d_out;           // (8,80,256,256)

    // 901120 points / 256 = 3520 blocks exactly.
    count_kernel<<<3520, 256>>>(geom);
    // Single-pass scatter, 352 threads (= 4*88) per row block.
    scatter_kernel<<<NROWS, 352>>>(x);
    // Transpose + restore zero-state for next call. 8*512 = 4096 blocks.
    transpose_zero_kernel<<<B_DIM * (NCELL / 128), 256>>>(out);
}

// round 13
// speedup vs baseline: 1.2500x; 1.2500x over previous
#include <cuda_runtime.h>

// Problem constants
#define B_DIM 8
#define D_DIM 40
#define H_DIM 32
#define W_DIM 88
#define C_DIM 80
#define QUADS (C_DIM / 4)
#define NX 256
#define NY 256
#define NCELL (NX * NY)                      // 65536 cells per batch
#define NPTS (B_DIM * D_DIM * H_DIM * W_DIM) // 901120 points
#define NROWS (B_DIM * D_DIM * H_DIM)        // 10240 rows of 88
#define DHW (D_DIM * H_DIM * W_DIM)          // 112640 points per batch
// NZ = 1

// Scratch accumulator (cell-major): (B, NCELL, C) fp32 = 168 MB. .bss zero.
// Entry invariant (maintained by transpose_zero_kernel): count table all-zero;
// every cell that will have count>=2 is zero (count==1 cells are fully
// overwritten by the sole-store; count==0 cells are never read).
__device__ float g_scratch[(long long)B_DIM * NCELL * C_DIM];
// Per-(b,cell) contributor count: 524288 ints = 2 MB. .bss zero.
__device__ int g_count[B_DIM * NCELL];
// Cached flat cell index per point (-1 = out of bounds): 3.6 MB.
__device__ int g_flat[NPTS];

// ---------------------------------------------------------------------------
// Count pass: 4 points per thread via 3 aligned float4 loads (48 B/thread).
// Computes each point's cell index (cached into g_flat) and bumps the
// per-(b,cell) contributor count. All 4 points share one b (DHW % 4 == 0).
// ---------------------------------------------------------------------------
__global__ void __launch_bounds__(256) count_kernel(
    const float4* __restrict__ geom4)  // (B, D, H, W, 3) viewed as float4
{
    const int tid = blockIdx.x * 256 + threadIdx.x;   // 0 .. NPTS/4-1 (exact)
    const int n0  = tid * 4;                          // first point index
    const int b   = n0 / DHW;                         // same for all 4 points

    const float4 f0 = __ldcs(&geom4[tid * 3 + 0]);
    const float4 f1 = __ldcs(&geom4[tid * 3 + 1]);
    const float4 f2 = __ldcs(&geom4[tid * 3 + 2]);

    const float px[4] = {f0.x, f0.w, f1.z, f2.y};
    const float py[4] = {f0.y, f1.x, f1.w, f2.z};
    const float pz[4] = {f0.z, f1.y, f2.x, f2.w};

    int flats[4];
    #pragma unroll
    for (int j = 0; j < 4; j++) {
        int flat = -1;
        const float gx = px[j], gy = py[j], gz = pz[j];
        if (gx >= -51.2f && gx < 51.2f &&
            gy >= -51.2f && gy < 51.2f &&
            gz >= -10.0f && gz < 10.0f) {
            // Match XLA: div-by-const lowered to mul-by-reciprocal (1/0.4 ==
            // 2.5f exactly in fp32). add-then-mul cannot be FMA-contracted.
            const float rx = (gx + 51.2f) * 2.5f;
            const float ry = (gy + 51.2f) * 2.5f;
            int ix = (int)rx;
            int iy = (int)ry;
            ix = min(max(ix, 0), NX - 1);
            iy = min(max(iy, 0), NY - 1);
            flat = ix * NY + iy;
        }
        flats[j] = flat;
    }

    *(int4*)&g_flat[n0] = make_int4(flats[0], flats[1], flats[2], flats[3]);

    #pragma unroll
    for (int j = 0; j < 4; j++) {
        if (flats[j] >= 0) {
            atomicAdd(&g_count[b * NCELL + flats[j]], 1);   // RED (no return)
        }
    }
}

// ---------------------------------------------------------------------------
// Scatter (round-11 form — proven): one block of 256 threads per (b, d, h)
// row of W=88 points. Modest per-thread MLP (round-12 lesson: front-batched
// MLP overflows the L1tex queue and regresses).
// Phase 1: threads 0..87 load the cached cell index + contributor count.
// Phase 2: loop over (quad q, w): 4 evict-first coalesced x loads; sole
//          contributor -> plain STG.128 (value + initialization, no LTS
//          atomic); otherwise red.global.add.v4.f32 onto the pre-zeroed base.
// ---------------------------------------------------------------------------
__global__ void __launch_bounds__(256) scatter_kernel(
    const float* __restrict__ x)      // (B, D, C, H, W)
{
    __shared__ int s_flat[W_DIM];
    __shared__ int s_cnt[W_DIM];

    const int bid = blockIdx.x;           // 0 .. NROWS-1
    const int h   = bid % H_DIM;
    const int bd  = bid / H_DIM;
    const int d   = bd % D_DIM;
    const int b   = bd / D_DIM;

    const int t = threadIdx.x;

    if (t < W_DIM) {
        const int flat = g_flat[bid * W_DIM + t];
        s_flat[t] = flat;
        s_cnt[t]  = (flat >= 0) ? __ldg(&g_count[b * NCELL + flat]) : 0;
    }
    __syncthreads();

    // x index: (((b*D+d)*C + c)*H + h)*W + w
    const long long x_base = ((long long)(b * D_DIM + d) * C_DIM * H_DIM + h) * W_DIM;
    const int c_stride = H_DIM * W_DIM;                       // 2816
    float* const sb = g_scratch + (long long)b * NCELL * C_DIM;

    const int total = QUADS * W_DIM;     // 20 * 88 = 1760
    for (int idx = t; idx < total; idx += blockDim.x) {
        const int q = idx / W_DIM;       // channel quad 0..19
        const int w = idx - q * W_DIM;
        const int flat = s_flat[w];
        if (flat >= 0) {
            // Evict-first: x is streamed once — keep L2 for the RMW set.
            const float* xp = x + x_base + (long long)(q * 4) * c_stride + w;
            float v0 = __ldcs(xp);
            float v1 = __ldcs(xp + c_stride);
            float v2 = __ldcs(xp + 2 * c_stride);
            float v3 = __ldcs(xp + 3 * c_stride);
            float* dst = sb + (long long)flat * C_DIM + q * 4;  // 16B aligned
            if (s_cnt[w] == 1) {
                // Sole contributor: plain vec store = value + initialization.
                *(float4*)dst = make_float4(v0, v1, v2, v3);
            } else {
                asm volatile("red.global.add.v4.f32 [%0], {%1, %2, %3, %4};"
                             :: "l"(dst), "f"(v0), "f"(v1), "f"(v2), "f"(v3)
                             : "memory");
            }
        }
    }
}

// ---------------------------------------------------------------------------
// Transpose + state restore: scratch (B, NCELL, C) -> out (B, C, NCELL).
// 128 cells x 80 channels per block, 512 threads (more warps to hide the
// LDS->STG dependency in the store phase).
//  - count==0 cells synthesized as zeros (no scratch read).
//  - Store phase: conflict-free scalar LDS (stride 81 == 17 mod 32) +
//    perfectly coalesced STG.32.
//  - Afterwards (well past the loads): zero the scratch of count>=2 cells
//    and zero the count words, restoring the entry invariant.
// ---------------------------------------------------------------------------
__global__ void __launch_bounds__(512) transpose_zero_kernel(float* __restrict__ out)
{
    __shared__ float tile[128][81];
    __shared__ int s_cnt[128];

    const int blk   = blockIdx.x;            // 0 .. B*512-1
    const int b     = blk >> 9;
    const int tile0 = (blk & 511) * 128;     // first cell of tile
    const int t     = threadIdx.x;

    if (t < 128) s_cnt[t] = __ldg(&g_count[b * NCELL + tile0 + t]);
    __syncthreads();

    float4* const src = (float4*)(g_scratch +
                        ((long long)b * NCELL + tile0) * C_DIM);

    // Load: 128 cells * 20 float4 = 2560 vec loads (5/thread), coalesced;
    // empty cells synthesized as zero without touching global.
    #pragma unroll
    for (int k = 0; k < 5; k++) {
        const int i    = t + k * 512;
        const int cell = i / 20;
        const int q    = i - cell * 20;
        float4 v = make_float4(0.f, 0.f, 0.f, 0.f);
        if (s_cnt[cell] > 0) v = __ldcs(&src[i]);
        tile[cell][q * 4 + 0] = v.x;
        tile[cell][q * 4 + 1] = v.y;
        tile[cell][q * 4 + 2] = v.z;
        tile[cell][q * 4 + 3] = v.w;
    }
    __syncthreads();

    // Store: 80 channels * 128 cells, scalar (20/thread). Lanes cover 32
    // consecutive cells of one channel: LDS conflict-free, STG.32 coalesced.
    float* ob = out + (long long)b * C_DIM * NCELL + tile0;
    #pragma unroll
    for (int k = 0; k < 20; k++) {
        const int i    = t + k * 512;
        const int c    = i >> 7;       // / 128
        const int cell = i & 127;
        __stcs(ob + (long long)c * NCELL + cell, tile[cell][c]);
    }

    // Restore scratch zeros for cells that needed a zero base this call
    // (count>=2). count==1 cells will be overwritten by next call's sole
    // store; count==0 cells are never read.
    #pragma unroll
    for (int k = 0; k < 5; k++) {
        const int i    = t + k * 512;
        const int cell = i / 20;
        if (s_cnt[cell] >= 2) {
            src[i] = make_float4(0.f, 0.f, 0.f, 0.f);
        }
    }

    // Restore count words to zero (128 ints = 32 int4).
    if (t < 32) {
        ((int4*)(g_count + b * NCELL + tile0))[t] = make_int4(0, 0, 0, 0);
    }
}

extern "C" void kernel_launch(void* const* d_in, const int* in_sizes, int n_in,
                              void* d_out, int out_size) {
    const float* geom = (const float*)d_in[0];   // (8,40,32,88,3)
    const float* x    = (const float*)d_in[1];   // (8,40,80,32,88)
    float* out        = (float*)d_out;           // (8,80,256,256)

    // 901120 points / 4 per thread / 256 = 880 blocks exactly.
    count_kernel<<<880, 256>>>((const float4*)geom);
    // Single-pass scatter (round-11 form), 256 threads per row block.
    scatter_kernel<<<NROWS, 256>>>(x);
    // Transpose + restore zero-state for next call. 8*512 = 4096 blocks.
    transpose_zero_kernel<<<B_DIM * (NCELL / 128), 512>>>(out);
}